// round 8
// baseline (speedup 1.0000x reference)
#include <cuda_runtime.h>
#include <cstdint>

#define BATCH 2
#define SEQ 2048
#define DMODEL 1024
#define NHEADS 16
#define DK 64
#define NTOK (BATCH*SEQ)          /* 4096 */
#define NEGVAL (-1000000000.0f)

// ---------------- scratch (device globals: allocation-free) ----------------
__device__ float g_q[(size_t)BATCH*NHEADS*SEQ*DK];   // 16 MB  [B,H,S,dk]
__device__ float g_k[(size_t)BATCH*NHEADS*SEQ*DK];   // 16 MB
__device__ float g_v[(size_t)BATCH*NHEADS*SEQ*DK];   // 16 MB
__device__ float g_ctx[(size_t)NTOK*DMODEL];         // 16 MB  [B,S,D]

// ============================ mma.sync helpers ==============================
__device__ __forceinline__ uint32_t cvt_tf32(float x) {
    uint32_t r; asm("cvt.rna.tf32.f32 %0, %1;" : "=r"(r) : "f"(x)); return r;
}
__device__ __forceinline__ void mma8(float* c, const uint32_t* a, const uint32_t* b) {
    asm volatile("mma.sync.aligned.m16n8k8.row.col.f32.tf32.tf32.f32 "
                 "{%0,%1,%2,%3}, {%4,%5,%6,%7}, {%8,%9}, {%0,%1,%2,%3};"
                 : "+f"(c[0]), "+f"(c[1]), "+f"(c[2]), "+f"(c[3])
                 : "r"(a[0]), "r"(a[1]), "r"(a[2]), "r"(a[3]),
                   "r"(b[0]), "r"(b[1]));
}

// ==================== tf32 3x GEMM core (HMMA path) =========================
#define RS 20
#define TILE_U32 (128*RS)

struct GemmSmem {
    uint32_t Ah[TILE_U32];
    uint32_t Al[TILE_U32];
    uint32_t Bh[TILE_U32];
    uint32_t Bl[TILE_U32];
};

__device__ __forceinline__ void gemm_tf32x3(
    const float* __restrict__ A, const float* __restrict__ B,
    int row0, int col0, GemmSmem* sm, float acc[4][4][4])
{
    const int tid = threadIdx.x;
    const int wid = tid >> 5, lane = tid & 31;
    const int g = lane >> 2, tig = lane & 3;
    const int warp_m = wid & 1;
    const int warp_n = wid >> 1;
    const int rA = warp_m * 64;
    const int cB = warp_n * 32;

#pragma unroll
    for (int mt = 0; mt < 4; mt++)
#pragma unroll
        for (int nt = 0; nt < 4; nt++)
#pragma unroll
            for (int q = 0; q < 4; q++) acc[mt][nt][q] = 0.f;

    for (int it = 0; it < DMODEL / 16; it++) {
        const int k0 = it * 16;
        __syncthreads();
#pragma unroll
        for (int l = 0; l < 2; l++) {
            int idx = tid + l * 256;
            int r = idx >> 2;
            int c4 = (idx & 3) * 4;
            float4 x = *(const float4*)&A[(size_t)(row0 + r) * DMODEL + k0 + c4];
            uint32_t h0 = cvt_tf32(x.x), h1 = cvt_tf32(x.y),
                     h2 = cvt_tf32(x.z), h3 = cvt_tf32(x.w);
            uint32_t l0 = cvt_tf32(x.x - __uint_as_float(h0));
            uint32_t l1 = cvt_tf32(x.y - __uint_as_float(h1));
            uint32_t l2 = cvt_tf32(x.z - __uint_as_float(h2));
            uint32_t l3 = cvt_tf32(x.w - __uint_as_float(h3));
            *(uint4*)&sm->Ah[r*RS + c4] = make_uint4(h0, h1, h2, h3);
            *(uint4*)&sm->Al[r*RS + c4] = make_uint4(l0, l1, l2, l3);
            float4 y = *(const float4*)&B[(size_t)(col0 + r) * DMODEL + k0 + c4];
            uint32_t j0 = cvt_tf32(y.x), j1 = cvt_tf32(y.y),
                     j2 = cvt_tf32(y.z), j3 = cvt_tf32(y.w);
            uint32_t m0 = cvt_tf32(y.x - __uint_as_float(j0));
            uint32_t m1 = cvt_tf32(y.y - __uint_as_float(j1));
            uint32_t m2 = cvt_tf32(y.z - __uint_as_float(j2));
            uint32_t m3 = cvt_tf32(y.w - __uint_as_float(j3));
            *(uint4*)&sm->Bh[r*RS + c4] = make_uint4(j0, j1, j2, j3);
            *(uint4*)&sm->Bl[r*RS + c4] = make_uint4(m0, m1, m2, m3);
        }
        __syncthreads();

#pragma unroll
        for (int ks = 0; ks < 2; ks++) {
            const int kk = ks * 8;
            uint32_t bh[4][2], bl[4][2];
#pragma unroll
            for (int nt = 0; nt < 4; nt++) {
                int nrow = cB + nt*8 + g;
                bh[nt][0] = sm->Bh[nrow*RS + kk + tig];
                bh[nt][1] = sm->Bh[nrow*RS + kk + tig + 4];
                bl[nt][0] = sm->Bl[nrow*RS + kk + tig];
                bl[nt][1] = sm->Bl[nrow*RS + kk + tig + 4];
            }
#pragma unroll
            for (int mt = 0; mt < 4; mt++) {
                int arow = rA + mt*16 + g;
                uint32_t ah[4], al[4];
                ah[0] = sm->Ah[arow*RS + kk + tig];
                ah[1] = sm->Ah[(arow+8)*RS + kk + tig];
                ah[2] = sm->Ah[arow*RS + kk + tig + 4];
                ah[3] = sm->Ah[(arow+8)*RS + kk + tig + 4];
                al[0] = sm->Al[arow*RS + kk + tig];
                al[1] = sm->Al[(arow+8)*RS + kk + tig];
                al[2] = sm->Al[arow*RS + kk + tig + 4];
                al[3] = sm->Al[(arow+8)*RS + kk + tig + 4];
#pragma unroll
                for (int nt = 0; nt < 4; nt++) {
                    mma8(acc[mt][nt], ah, bh[nt]);
                    mma8(acc[mt][nt], ah, bl[nt]);
                    mma8(acc[mt][nt], al, bh[nt]);
                }
            }
        }
    }
}

// ============================================================================
// Fused QKV projections
// ============================================================================
__global__ __launch_bounds__(256, 2)
void k_projmma(const float* __restrict__ Qin, const float* __restrict__ Kin,
               const float* __restrict__ Vin,
               const float* __restrict__ Wq, const float* __restrict__ Wk,
               const float* __restrict__ Wv,
               const float* __restrict__ bq, const float* __restrict__ bk,
               const float* __restrict__ bv)
{
    __shared__ GemmSmem sm;
    const int z = blockIdx.z;
    const float* X = (z == 0) ? Qin : (z == 1) ? Kin : Vin;
    const float* W = (z == 0) ? Wq  : (z == 1) ? Wk  : Wv;
    const float* bias = (z == 0) ? bq : (z == 1) ? bk : bv;
    float* out = (z == 0) ? g_q : (z == 1) ? g_k : g_v;
    const int row0 = blockIdx.x * 128;
    const int col0 = blockIdx.y * 128;

    float acc[4][4][4];
    gemm_tf32x3(X, W, row0, col0, &sm, acc);

    const int tid = threadIdx.x;
    const int wid = tid >> 5, lane = tid & 31;
    const int g = lane >> 2, tig = lane & 3;
    const int warp_m = wid & 1, warp_n = wid >> 1;

#pragma unroll
    for (int nt = 0; nt < 4; nt++) {
        int col = col0 + warp_n*32 + nt*8 + tig*2;
        float b0 = bias[col], b1 = bias[col + 1];
        int h = col >> 6, dd = col & 63;
#pragma unroll
        for (int mt = 0; mt < 4; mt++) {
            int token = row0 + warp_m*64 + mt*16 + g;
            int b = token >> 11, s = token & (SEQ - 1);
            float* base = &out[(((size_t)(b*NHEADS + h))*SEQ + s)*DK + dd];
            *(float2*)base = make_float2(acc[mt][nt][0] + b0, acc[mt][nt][1] + b1);
            float* base2 = base + (size_t)8 * DK;
            *(float2*)base2 = make_float2(acc[mt][nt][2] + b0, acc[mt][nt][3] + b1);
        }
    }
}

// ============================================================================
// Output GEMM: out = g_ctx @ Wo^T + bo + resid
// ============================================================================
__global__ __launch_bounds__(256, 2)
void k_outmma(const float* __restrict__ W, const float* __restrict__ bias,
              const float* __restrict__ resid, float* __restrict__ out)
{
    __shared__ GemmSmem sm;
    const int row0 = blockIdx.x * 128;
    const int col0 = blockIdx.y * 128;

    float acc[4][4][4];
    gemm_tf32x3(g_ctx, W, row0, col0, &sm, acc);

    const int tid = threadIdx.x;
    const int wid = tid >> 5, lane = tid & 31;
    const int g = lane >> 2, tig = lane & 3;
    const int warp_m = wid & 1, warp_n = wid >> 1;

#pragma unroll
    for (int nt = 0; nt < 4; nt++) {
        int col = col0 + warp_n*32 + nt*8 + tig*2;
        float b0 = bias[col], b1 = bias[col + 1];
#pragma unroll
        for (int mt = 0; mt < 4; mt++) {
            int token = row0 + warp_m*64 + mt*16 + g;
            size_t gi = (size_t)token * DMODEL + col;
            float2 r0 = *(const float2*)&resid[gi];
            float2 r1 = *(const float2*)&resid[gi + 8*DMODEL];
            *(float2*)&out[gi] =
                make_float2(acc[mt][nt][0] + b0 + r0.x, acc[mt][nt][1] + b1 + r0.y);
            *(float2*)&out[gi + 8*DMODEL] =
                make_float2(acc[mt][nt][2] + b0 + r1.x, acc[mt][nt][3] + b1 + r1.y);
        }
    }
}

// ============================================================================
// Fused attention, HMMA tf32x3 with interleaved hi/lo tiles + double buffer.
// CTA = 128 q-rows x one (b,h). 8 warps, each warp owns 16 q-rows.
// K/V tile layout: buf[r*VS + k*2 + {0=hi,1=lo}], VS=160 floats (640B rows).
// One __syncthreads per k-tile; mask read directly from gmem in epilogue.
// ============================================================================
#define KTILE 64
#define NKT (SEQ/KTILE)            /* 32 */
#define VS 160                     /* floats per buffer row */
#define BUF_FLOATS (KTILE*VS)      /* 10240 */
#define ATTN_SMEM (2*BUF_FLOATS*4) /* 81920 bytes */

// stage a 64x64 f32 tile as interleaved {hi,lo}
__device__ __forceinline__ void stage_hl(const float* __restrict__ src,
                                         float* __restrict__ buf, int tid)
{
#pragma unroll
    for (int l = 0; l < 4; l++) {
        int idx = tid + l * 256;            // 0..1023
        int r = idx >> 4, c4 = (idx & 15) * 4;
        float4 x = *(const float4*)&src[(size_t)r * DK + c4];
        uint32_t h0 = cvt_tf32(x.x), h1 = cvt_tf32(x.y),
                 h2 = cvt_tf32(x.z), h3 = cvt_tf32(x.w);
        float l0 = __uint_as_float(cvt_tf32(x.x - __uint_as_float(h0)));
        float l1 = __uint_as_float(cvt_tf32(x.y - __uint_as_float(h1)));
        float l2 = __uint_as_float(cvt_tf32(x.z - __uint_as_float(h2)));
        float l3 = __uint_as_float(cvt_tf32(x.w - __uint_as_float(h3)));
        float* dst = &buf[r*VS + c4*2];
        *(float4*)dst       = make_float4(__uint_as_float(h0), l0,
                                          __uint_as_float(h1), l1);
        *(float4*)(dst + 4) = make_float4(__uint_as_float(h2), l2,
                                          __uint_as_float(h3), l3);
    }
}

__global__ __launch_bounds__(256, 2)
void k_attn_mma(const unsigned char* __restrict__ mask,
                float* __restrict__ scores_g, float* __restrict__ attn_g)
{
    extern __shared__ float smf[];
    float* buf0 = smf;
    float* buf1 = smf + BUF_FLOATS;

    const int tid = threadIdx.x;
    const int wid = tid >> 5, lane = tid & 31;
    const int g = lane >> 2, tig = lane & 3;
    const int qb = blockIdx.x, bh = blockIdx.y;
    const int b = bh >> 4, h = bh & 15;
    const int qr0 = qb * 128;
    const float* qp = g_q + (size_t)bh * SEQ * DK;
    const float* kp = g_k + (size_t)bh * SEQ * DK;
    const float* vp = g_v + (size_t)bh * SEQ * DK;
    float* srow = scores_g + ((size_t)bh * SEQ + qr0) * SEQ;
    float* arow = attn_g   + ((size_t)bh * SEQ + qr0) * SEQ;
    const int r0 = wid*16 + g, r1 = r0 + 8;

    // ---- stage Q raw (128x68 = 34816B, fits buf0); extract persistent frags -
#pragma unroll
    for (int l = 0; l < 8; l++) {
        int idx = tid + l * 256;
        int r = idx >> 4, c4 = (idx & 15) * 4;
        float4 q = *(const float4*)&qp[(size_t)(qr0 + r) * DK + c4];
        *(float4*)&buf0[r*68 + c4] = q;
    }
    __syncthreads();
    uint32_t aQh[8][4], aQl[8][4];
#pragma unroll
    for (int ks = 0; ks < 8; ks++) {
        float q0 = buf0[r0*68 + ks*8 + tig];
        float q1 = buf0[r1*68 + ks*8 + tig];
        float q2 = buf0[r0*68 + ks*8 + tig + 4];
        float q3 = buf0[r1*68 + ks*8 + tig + 4];
        aQh[ks][0] = cvt_tf32(q0); aQl[ks][0] = cvt_tf32(q0 - __uint_as_float(aQh[ks][0]));
        aQh[ks][1] = cvt_tf32(q1); aQl[ks][1] = cvt_tf32(q1 - __uint_as_float(aQh[ks][1]));
        aQh[ks][2] = cvt_tf32(q2); aQl[ks][2] = cvt_tf32(q2 - __uint_as_float(aQh[ks][2]));
        aQh[ks][3] = cvt_tf32(q3); aQl[ks][3] = cvt_tf32(q3 - __uint_as_float(aQh[ks][3]));
    }
    __syncthreads();

    float mrow[2] = {-3.0e38f, -3.0e38f};
    float lrow[2] = {0.f, 0.f};

    // ======================= PASS A: scores + stats =======================
    stage_hl(kp, buf0, tid);               // K tile 0 -> buf0
    __syncthreads();

    for (int kt = 0; kt < NKT; kt++) {
        float* cur = (kt & 1) ? buf1 : buf0;
        float* nxt = (kt & 1) ? buf0 : buf1;
        if (kt + 1 < NKT)
            stage_hl(kp + (size_t)(kt+1)*KTILE*DK, nxt, tid);

        float acc[8][4];
#pragma unroll
        for (int nt = 0; nt < 8; nt++)
#pragma unroll
            for (int q = 0; q < 4; q++) acc[nt][q] = 0.f;

#pragma unroll
        for (int nt = 0; nt < 8; nt++) {
            const float* bp = &cur[(nt*8 + g) * VS];
#pragma unroll
            for (int ks = 0; ks < 8; ks++) {
                float2 p0 = *(const float2*)&bp[(ks*8 + tig) * 2];
                float2 p1 = *(const float2*)&bp[(ks*8 + tig + 4) * 2];
                uint32_t bhv[2] = {__float_as_uint(p0.x), __float_as_uint(p1.x)};
                uint32_t blv[2] = {__float_as_uint(p0.y), __float_as_uint(p1.y)};
                mma8(acc[nt], aQh[ks], bhv);
                mma8(acc[nt], aQh[ks], blv);
                mma8(acc[nt], aQl[ks], bhv);
            }
        }

        // epilogue: scale + mask (direct gmem) + stats + store scores
        const unsigned char* mk0 = mask + ((size_t)b*SEQ + qr0 + r0)*SEQ + kt*KTILE;
        const unsigned char* mk1 = mask + ((size_t)b*SEQ + qr0 + r1)*SEQ + kt*KTILE;
        float mn0 = mrow[0], mn1 = mrow[1];
#pragma unroll
        for (int nt = 0; nt < 8; nt++) {
            int c = nt*8 + tig*2;
            unsigned short m0 = *(const unsigned short*)(mk0 + c);
            unsigned short m1 = *(const unsigned short*)(mk1 + c);
            acc[nt][0] = (m0 & 0xff) ? NEGVAL : acc[nt][0] * 0.125f;
            acc[nt][1] = (m0 >> 8)  ? NEGVAL : acc[nt][1] * 0.125f;
            acc[nt][2] = (m1 & 0xff) ? NEGVAL : acc[nt][2] * 0.125f;
            acc[nt][3] = (m1 >> 8)  ? NEGVAL : acc[nt][3] * 0.125f;
            mn0 = fmaxf(mn0, fmaxf(acc[nt][0], acc[nt][1]));
            mn1 = fmaxf(mn1, fmaxf(acc[nt][2], acc[nt][3]));
        }
        mn0 = fmaxf(mn0, __shfl_xor_sync(0xffffffffu, mn0, 1));
        mn0 = fmaxf(mn0, __shfl_xor_sync(0xffffffffu, mn0, 2));
        mn1 = fmaxf(mn1, __shfl_xor_sync(0xffffffffu, mn1, 1));
        mn1 = fmaxf(mn1, __shfl_xor_sync(0xffffffffu, mn1, 2));
        float ts0 = 0.f, ts1 = 0.f;
#pragma unroll
        for (int nt = 0; nt < 8; nt++) {
            ts0 += __expf(acc[nt][0] - mn0) + __expf(acc[nt][1] - mn0);
            ts1 += __expf(acc[nt][2] - mn1) + __expf(acc[nt][3] - mn1);
        }
        ts0 += __shfl_xor_sync(0xffffffffu, ts0, 1);
        ts0 += __shfl_xor_sync(0xffffffffu, ts0, 2);
        ts1 += __shfl_xor_sync(0xffffffffu, ts1, 1);
        ts1 += __shfl_xor_sync(0xffffffffu, ts1, 2);
        lrow[0] = lrow[0] * __expf(mrow[0] - mn0) + ts0;  mrow[0] = mn0;
        lrow[1] = lrow[1] * __expf(mrow[1] - mn1) + ts1;  mrow[1] = mn1;
#pragma unroll
        for (int nt = 0; nt < 8; nt++) {
            int c = kt*KTILE + nt*8 + tig*2;
            *(float2*)&srow[(size_t)r0 * SEQ + c] = make_float2(acc[nt][0], acc[nt][1]);
            *(float2*)&srow[(size_t)r1 * SEQ + c] = make_float2(acc[nt][2], acc[nt][3]);
        }
        __syncthreads();
    }

    const float inv0 = 1.0f / lrow[0];
    const float inv1 = 1.0f / lrow[1];

    // ======================= PASS B: attn + E@V ===========================
    float co[8][4];
#pragma unroll
    for (int nt = 0; nt < 8; nt++)
#pragma unroll
        for (int q = 0; q < 4; q++) co[nt][q] = 0.f;

    stage_hl(vp + (size_t)(NKT-1)*KTILE*DK, buf1, tid);   // V tile 31 -> buf1
    __syncthreads();

    for (int kt = NKT - 1; kt >= 0; kt--) {
        float* cur = (kt & 1) ? buf1 : buf0;
        if (kt > 0)
            stage_hl(vp + (size_t)(kt-1)*KTILE*DK, ((kt-1)&1) ? buf1 : buf0, tid);

#pragma unroll
        for (int ks = 0; ks < 8; ks++) {
            const size_t c0 = (size_t)kt*KTILE + ks*8 + tig;
            float s0 = srow[(size_t)r0 * SEQ + c0];
            float s1 = srow[(size_t)r1 * SEQ + c0];
            float s2 = srow[(size_t)r0 * SEQ + c0 + 4];
            float s3 = srow[(size_t)r1 * SEQ + c0 + 4];
            float e0 = __expf(s0 - mrow[0]) * inv0;
            float e1 = __expf(s1 - mrow[1]) * inv1;
            float e2 = __expf(s2 - mrow[0]) * inv0;
            float e3 = __expf(s3 - mrow[1]) * inv1;
            arow[(size_t)r0 * SEQ + c0]     = e0;
            arow[(size_t)r1 * SEQ + c0]     = e1;
            arow[(size_t)r0 * SEQ + c0 + 4] = e2;
            arow[(size_t)r1 * SEQ + c0 + 4] = e3;
            uint32_t aeh[4], ael[4];
            aeh[0] = cvt_tf32(e0); ael[0] = cvt_tf32(e0 - __uint_as_float(aeh[0]));
            aeh[1] = cvt_tf32(e1); ael[1] = cvt_tf32(e1 - __uint_as_float(aeh[1]));
            aeh[2] = cvt_tf32(e2); ael[2] = cvt_tf32(e2 - __uint_as_float(aeh[2]));
            aeh[3] = cvt_tf32(e3); ael[3] = cvt_tf32(e3 - __uint_as_float(aeh[3]));
            const float* vr0 = &cur[(ks*8 + tig) * VS];
            const float* vr1 = &cur[(ks*8 + tig + 4) * VS];
#pragma unroll
            for (int nt = 0; nt < 8; nt++) {
                int d2 = (nt*8 + g) * 2;
                float2 p0 = *(const float2*)&vr0[d2];
                float2 p1 = *(const float2*)&vr1[d2];
                uint32_t bhv[2] = {__float_as_uint(p0.x), __float_as_uint(p1.x)};
                uint32_t blv[2] = {__float_as_uint(p0.y), __float_as_uint(p1.y)};
                mma8(co[nt], aeh, bhv);
                mma8(co[nt], aeh, blv);
                mma8(co[nt], ael, bhv);
            }
        }
        __syncthreads();
    }

    // write ctx [B,S,D]
#pragma unroll
    for (int nt = 0; nt < 8; nt++) {
        int d = nt*8 + tig*2;
        *(float2*)&g_ctx[((size_t)(b*SEQ) + qr0 + r0) * DMODEL + h*DK + d] =
            make_float2(co[nt][0], co[nt][1]);
        *(float2*)&g_ctx[((size_t)(b*SEQ) + qr0 + r1) * DMODEL + h*DK + d] =
            make_float2(co[nt][2], co[nt][3]);
    }
}

// ============================================================================
extern "C" void kernel_launch(void* const* d_in, const int* in_sizes, int n_in,
                              void* d_out, int out_size)
{
    const float* Q  = (const float*)d_in[0];
    const float* K  = (const float*)d_in[1];
    const float* V  = (const float*)d_in[2];
    const unsigned char* mask = (const unsigned char*)d_in[3];
    const float* Wq = (const float*)d_in[4];  const float* bq = (const float*)d_in[5];
    const float* Wk = (const float*)d_in[6];  const float* bk = (const float*)d_in[7];
    const float* Wv = (const float*)d_in[8];  const float* bv = (const float*)d_in[9];
    const float* Wo = (const float*)d_in[10]; const float* bo = (const float*)d_in[11];

    float* out    = (float*)d_out;
    float* attn   = out + (size_t)NTOK * DMODEL;
    float* scores = attn + (size_t)BATCH * NHEADS * SEQ * SEQ;

    cudaFuncSetAttribute(k_attn_mma, cudaFuncAttributeMaxDynamicSharedMemorySize,
                         ATTN_SMEM);

    dim3 gp(NTOK / 128, DMODEL / 128, 3);       // 32 x 8 x 3
    k_projmma<<<gp, 256>>>(Q, K, V, Wq, Wk, Wv, bq, bk, bv);

    dim3 gf(SEQ / 128, BATCH * NHEADS);         // 16 x 32
    k_attn_mma<<<gf, 256, ATTN_SMEM>>>(mask, scores, attn);

    dim3 go(NTOK / 128, DMODEL / 128);          // 32 x 8
    k_outmma<<<go, 256>>>(Wo, bo, Q, out);
}

// round 9
// speedup vs baseline: 1.4474x; 1.4474x over previous
#include <cuda_runtime.h>
#include <cstdint>

#define BATCH 2
#define SEQ 2048
#define DMODEL 1024
#define NHEADS 16
#define DK 64
#define NTOK (BATCH*SEQ)          /* 4096 */
#define NEGVAL (-1000000000.0f)

// ---------------- scratch (device globals: allocation-free) ----------------
__device__ float g_q[(size_t)BATCH*NHEADS*SEQ*DK];   // 16 MB  [B,H,S,dk]
__device__ float g_k[(size_t)BATCH*NHEADS*SEQ*DK];   // 16 MB
__device__ float g_v[(size_t)BATCH*NHEADS*SEQ*DK];   // 16 MB
__device__ float g_ctx[(size_t)NTOK*DMODEL];         // 16 MB  [B,S,D]

// ============================ mma.sync helpers ==============================
__device__ __forceinline__ uint32_t cvt_tf32(float x) {
    uint32_t r; asm("cvt.rna.tf32.f32 %0, %1;" : "=r"(r) : "f"(x)); return r;
}
__device__ __forceinline__ void mma8(float* c, const uint32_t* a, const uint32_t* b) {
    asm volatile("mma.sync.aligned.m16n8k8.row.col.f32.tf32.tf32.f32 "
                 "{%0,%1,%2,%3}, {%4,%5,%6,%7}, {%8,%9}, {%0,%1,%2,%3};"
                 : "+f"(c[0]), "+f"(c[1]), "+f"(c[2]), "+f"(c[3])
                 : "r"(a[0]), "r"(a[1]), "r"(a[2]), "r"(a[3]),
                   "r"(b[0]), "r"(b[1]));
}

// ==================== tf32 3x GEMM core (HMMA path) =========================
#define RS 20
#define TILE_U32 (128*RS)

struct GemmSmem {
    uint32_t Ah[TILE_U32];
    uint32_t Al[TILE_U32];
    uint32_t Bh[TILE_U32];
    uint32_t Bl[TILE_U32];
};

__device__ __forceinline__ void gemm_tf32x3(
    const float* __restrict__ A, const float* __restrict__ B,
    int row0, int col0, GemmSmem* sm, float acc[4][4][4])
{
    const int tid = threadIdx.x;
    const int wid = tid >> 5, lane = tid & 31;
    const int g = lane >> 2, tig = lane & 3;
    const int warp_m = wid & 1;
    const int warp_n = wid >> 1;
    const int rA = warp_m * 64;
    const int cB = warp_n * 32;

#pragma unroll
    for (int mt = 0; mt < 4; mt++)
#pragma unroll
        for (int nt = 0; nt < 4; nt++)
#pragma unroll
            for (int q = 0; q < 4; q++) acc[mt][nt][q] = 0.f;

    for (int it = 0; it < DMODEL / 16; it++) {
        const int k0 = it * 16;
        __syncthreads();
#pragma unroll
        for (int l = 0; l < 2; l++) {
            int idx = tid + l * 256;
            int r = idx >> 2;
            int c4 = (idx & 3) * 4;
            float4 x = *(const float4*)&A[(size_t)(row0 + r) * DMODEL + k0 + c4];
            uint32_t h0 = cvt_tf32(x.x), h1 = cvt_tf32(x.y),
                     h2 = cvt_tf32(x.z), h3 = cvt_tf32(x.w);
            uint32_t l0 = cvt_tf32(x.x - __uint_as_float(h0));
            uint32_t l1 = cvt_tf32(x.y - __uint_as_float(h1));
            uint32_t l2 = cvt_tf32(x.z - __uint_as_float(h2));
            uint32_t l3 = cvt_tf32(x.w - __uint_as_float(h3));
            *(uint4*)&sm->Ah[r*RS + c4] = make_uint4(h0, h1, h2, h3);
            *(uint4*)&sm->Al[r*RS + c4] = make_uint4(l0, l1, l2, l3);
            float4 y = *(const float4*)&B[(size_t)(col0 + r) * DMODEL + k0 + c4];
            uint32_t j0 = cvt_tf32(y.x), j1 = cvt_tf32(y.y),
                     j2 = cvt_tf32(y.z), j3 = cvt_tf32(y.w);
            uint32_t m0 = cvt_tf32(y.x - __uint_as_float(j0));
            uint32_t m1 = cvt_tf32(y.y - __uint_as_float(j1));
            uint32_t m2 = cvt_tf32(y.z - __uint_as_float(j2));
            uint32_t m3 = cvt_tf32(y.w - __uint_as_float(j3));
            *(uint4*)&sm->Bh[r*RS + c4] = make_uint4(j0, j1, j2, j3);
            *(uint4*)&sm->Bl[r*RS + c4] = make_uint4(m0, m1, m2, m3);
        }
        __syncthreads();

#pragma unroll
        for (int ks = 0; ks < 2; ks++) {
            const int kk = ks * 8;
            uint32_t bh[4][2], bl[4][2];
#pragma unroll
            for (int nt = 0; nt < 4; nt++) {
                int nrow = cB + nt*8 + g;
                bh[nt][0] = sm->Bh[nrow*RS + kk + tig];
                bh[nt][1] = sm->Bh[nrow*RS + kk + tig + 4];
                bl[nt][0] = sm->Bl[nrow*RS + kk + tig];
                bl[nt][1] = sm->Bl[nrow*RS + kk + tig + 4];
            }
#pragma unroll
            for (int mt = 0; mt < 4; mt++) {
                int arow = rA + mt*16 + g;
                uint32_t ah[4], al[4];
                ah[0] = sm->Ah[arow*RS + kk + tig];
                ah[1] = sm->Ah[(arow+8)*RS + kk + tig];
                ah[2] = sm->Ah[arow*RS + kk + tig + 4];
                ah[3] = sm->Ah[(arow+8)*RS + kk + tig + 4];
                al[0] = sm->Al[arow*RS + kk + tig];
                al[1] = sm->Al[(arow+8)*RS + kk + tig];
                al[2] = sm->Al[arow*RS + kk + tig + 4];
                al[3] = sm->Al[(arow+8)*RS + kk + tig + 4];
#pragma unroll
                for (int nt = 0; nt < 4; nt++) {
                    mma8(acc[mt][nt], ah, bh[nt]);
                    mma8(acc[mt][nt], ah, bl[nt]);
                    mma8(acc[mt][nt], al, bh[nt]);
                }
            }
        }
    }
}

// ============================================================================
// Fused QKV projections
// ============================================================================
__global__ __launch_bounds__(256, 2)
void k_projmma(const float* __restrict__ Qin, const float* __restrict__ Kin,
               const float* __restrict__ Vin,
               const float* __restrict__ Wq, const float* __restrict__ Wk,
               const float* __restrict__ Wv,
               const float* __restrict__ bq, const float* __restrict__ bk,
               const float* __restrict__ bv)
{
    __shared__ GemmSmem sm;
    const int z = blockIdx.z;
    const float* X = (z == 0) ? Qin : (z == 1) ? Kin : Vin;
    const float* W = (z == 0) ? Wq  : (z == 1) ? Wk  : Wv;
    const float* bias = (z == 0) ? bq : (z == 1) ? bk : bv;
    float* out = (z == 0) ? g_q : (z == 1) ? g_k : g_v;
    const int row0 = blockIdx.x * 128;
    const int col0 = blockIdx.y * 128;

    float acc[4][4][4];
    gemm_tf32x3(X, W, row0, col0, &sm, acc);

    const int tid = threadIdx.x;
    const int wid = tid >> 5, lane = tid & 31;
    const int g = lane >> 2, tig = lane & 3;
    const int warp_m = wid & 1, warp_n = wid >> 1;

#pragma unroll
    for (int nt = 0; nt < 4; nt++) {
        int col = col0 + warp_n*32 + nt*8 + tig*2;
        float b0 = bias[col], b1 = bias[col + 1];
        int h = col >> 6, dd = col & 63;
#pragma unroll
        for (int mt = 0; mt < 4; mt++) {
            int token = row0 + warp_m*64 + mt*16 + g;
            int b = token >> 11, s = token & (SEQ - 1);
            float* base = &out[(((size_t)(b*NHEADS + h))*SEQ + s)*DK + dd];
            *(float2*)base = make_float2(acc[mt][nt][0] + b0, acc[mt][nt][1] + b1);
            float* base2 = base + (size_t)8 * DK;
            *(float2*)base2 = make_float2(acc[mt][nt][2] + b0, acc[mt][nt][3] + b1);
        }
    }
}

// ============================================================================
// Output GEMM: out = g_ctx @ Wo^T + bo + resid
// ============================================================================
__global__ __launch_bounds__(256, 2)
void k_outmma(const float* __restrict__ W, const float* __restrict__ bias,
              const float* __restrict__ resid, float* __restrict__ out)
{
    __shared__ GemmSmem sm;
    const int row0 = blockIdx.x * 128;
    const int col0 = blockIdx.y * 128;

    float acc[4][4][4];
    gemm_tf32x3(g_ctx, W, row0, col0, &sm, acc);

    const int tid = threadIdx.x;
    const int wid = tid >> 5, lane = tid & 31;
    const int g = lane >> 2, tig = lane & 3;
    const int warp_m = wid & 1, warp_n = wid >> 1;

#pragma unroll
    for (int nt = 0; nt < 4; nt++) {
        int col = col0 + warp_n*32 + nt*8 + tig*2;
        float b0 = bias[col], b1 = bias[col + 1];
#pragma unroll
        for (int mt = 0; mt < 4; mt++) {
            int token = row0 + warp_m*64 + mt*16 + g;
            size_t gi = (size_t)token * DMODEL + col;
            float2 r0 = *(const float2*)&resid[gi];
            float2 r1 = *(const float2*)&resid[gi + 8*DMODEL];
            *(float2*)&out[gi] =
                make_float2(acc[mt][nt][0] + b0 + r0.x, acc[mt][nt][1] + b1 + r0.y);
            *(float2*)&out[gi + 8*DMODEL] =
                make_float2(acc[mt][nt][2] + b0 + r1.x, acc[mt][nt][3] + b1 + r1.y);
        }
    }
}

// ============================================================================
// Fused attention, HMMA tf32x3. Round-7 conflict-free hi/lo layout
// (separate tiles, stride 68 pass A / 72 pass B, scalar LDS) + double-buffered
// K/V tiles (one __syncthreads per tile) + mask direct from gmem.
// CTA = 128 q-rows x one (b,h). 8 warps, each warp owns 16 q-rows.
// ============================================================================
#define KTILE 64
#define NKT (SEQ/KTILE)            /* 32 */
#define LO_OFF 4608                /* floats: 64 rows x stride<=72 */
#define BUF_FL 9216                /* floats per buffer (hi + lo) */
#define ATTN_SMEM (2*BUF_FL*4)     /* 73728 bytes */

// stage a 64x64 f32 tile into buf as hi (stride) + lo (offset LO_OFF, stride)
__device__ __forceinline__ void stage_hl(const float* __restrict__ src,
                                         float* __restrict__ buf,
                                         int tid, int stride)
{
#pragma unroll
    for (int l = 0; l < 4; l++) {
        int idx = tid + l * 256;            // 0..1023
        int r = idx >> 4, c4 = (idx & 15) * 4;
        float4 x = *(const float4*)&src[(size_t)r * DK + c4];
        uint32_t h0 = cvt_tf32(x.x), h1 = cvt_tf32(x.y),
                 h2 = cvt_tf32(x.z), h3 = cvt_tf32(x.w);
        float4 lo = make_float4(
            __uint_as_float(cvt_tf32(x.x - __uint_as_float(h0))),
            __uint_as_float(cvt_tf32(x.y - __uint_as_float(h1))),
            __uint_as_float(cvt_tf32(x.z - __uint_as_float(h2))),
            __uint_as_float(cvt_tf32(x.w - __uint_as_float(h3))));
        *(float4*)&buf[r*stride + c4] = make_float4(
            __uint_as_float(h0), __uint_as_float(h1),
            __uint_as_float(h2), __uint_as_float(h3));
        *(float4*)&buf[LO_OFF + r*stride + c4] = lo;
    }
}

__global__ __launch_bounds__(256, 2)
void k_attn_mma(const unsigned char* __restrict__ mask,
                float* __restrict__ scores_g, float* __restrict__ attn_g)
{
    extern __shared__ float smf[];
    float* buf0 = smf;
    float* buf1 = smf + BUF_FL;

    const int tid = threadIdx.x;
    const int wid = tid >> 5, lane = tid & 31;
    const int g = lane >> 2, tig = lane & 3;
    const int qb = blockIdx.x, bh = blockIdx.y;
    const int b = bh >> 4, h = bh & 15;
    const int qr0 = qb * 128;
    const float* qp = g_q + (size_t)bh * SEQ * DK;
    const float* kp = g_k + (size_t)bh * SEQ * DK;
    const float* vp = g_v + (size_t)bh * SEQ * DK;
    float* srow = scores_g + ((size_t)bh * SEQ + qr0) * SEQ;
    float* arow = attn_g   + ((size_t)bh * SEQ + qr0) * SEQ;
    const int r0 = wid*16 + g, r1 = r0 + 8;

    // ---- stage Q raw (128x68 = 8704 floats, fits buf0); persistent frags ----
#pragma unroll
    for (int l = 0; l < 8; l++) {
        int idx = tid + l * 256;
        int r = idx >> 4, c4 = (idx & 15) * 4;
        float4 q = *(const float4*)&qp[(size_t)(qr0 + r) * DK + c4];
        *(float4*)&buf0[r*68 + c4] = q;
    }
    __syncthreads();
    uint32_t aQh[8][4], aQl[8][4];
#pragma unroll
    for (int ks = 0; ks < 8; ks++) {
        float q0 = buf0[r0*68 + ks*8 + tig];
        float q1 = buf0[r1*68 + ks*8 + tig];
        float q2 = buf0[r0*68 + ks*8 + tig + 4];
        float q3 = buf0[r1*68 + ks*8 + tig + 4];
        aQh[ks][0] = cvt_tf32(q0); aQl[ks][0] = cvt_tf32(q0 - __uint_as_float(aQh[ks][0]));
        aQh[ks][1] = cvt_tf32(q1); aQl[ks][1] = cvt_tf32(q1 - __uint_as_float(aQh[ks][1]));
        aQh[ks][2] = cvt_tf32(q2); aQl[ks][2] = cvt_tf32(q2 - __uint_as_float(aQh[ks][2]));
        aQh[ks][3] = cvt_tf32(q3); aQl[ks][3] = cvt_tf32(q3 - __uint_as_float(aQh[ks][3]));
    }
    __syncthreads();

    float mrow[2] = {-3.0e38f, -3.0e38f};
    float lrow[2] = {0.f, 0.f};

    // ======================= PASS A: scores + stats =======================
    stage_hl(kp, buf0, tid, 68);            // K tile 0 -> buf0
    __syncthreads();

    for (int kt = 0; kt < NKT; kt++) {
        float* cur = (kt & 1) ? buf1 : buf0;
        float* nxt = (kt & 1) ? buf0 : buf1;
        if (kt + 1 < NKT)
            stage_hl(kp + (size_t)(kt+1)*KTILE*DK, nxt, tid, 68);

        const float* Sh = cur;
        const float* Sl = cur + LO_OFF;

        float acc[8][4];
#pragma unroll
        for (int nt = 0; nt < 8; nt++)
#pragma unroll
            for (int q = 0; q < 4; q++) acc[nt][q] = 0.f;

#pragma unroll
        for (int nt = 0; nt < 8; nt++) {
            const int nr = nt*8 + g;
#pragma unroll
            for (int ks = 0; ks < 8; ks++) {
                uint32_t bhv[2], blv[2];
                bhv[0] = __float_as_uint(Sh[nr*68 + ks*8 + tig]);
                bhv[1] = __float_as_uint(Sh[nr*68 + ks*8 + tig + 4]);
                blv[0] = __float_as_uint(Sl[nr*68 + ks*8 + tig]);
                blv[1] = __float_as_uint(Sl[nr*68 + ks*8 + tig + 4]);
                mma8(acc[nt], aQh[ks], bhv);
                mma8(acc[nt], aQh[ks], blv);
                mma8(acc[nt], aQl[ks], bhv);
            }
        }

        // epilogue: scale + mask (direct gmem) + stats + store scores
        const unsigned char* mk0 = mask + ((size_t)b*SEQ + qr0 + r0)*SEQ + kt*KTILE;
        const unsigned char* mk1 = mask + ((size_t)b*SEQ + qr0 + r1)*SEQ + kt*KTILE;
        float mn0 = mrow[0], mn1 = mrow[1];
#pragma unroll
        for (int nt = 0; nt < 8; nt++) {
            int c = nt*8 + tig*2;
            unsigned short m0 = *(const unsigned short*)(mk0 + c);
            unsigned short m1 = *(const unsigned short*)(mk1 + c);
            acc[nt][0] = (m0 & 0xff) ? NEGVAL : acc[nt][0] * 0.125f;
            acc[nt][1] = (m0 >> 8)  ? NEGVAL : acc[nt][1] * 0.125f;
            acc[nt][2] = (m1 & 0xff) ? NEGVAL : acc[nt][2] * 0.125f;
            acc[nt][3] = (m1 >> 8)  ? NEGVAL : acc[nt][3] * 0.125f;
            mn0 = fmaxf(mn0, fmaxf(acc[nt][0], acc[nt][1]));
            mn1 = fmaxf(mn1, fmaxf(acc[nt][2], acc[nt][3]));
        }
        mn0 = fmaxf(mn0, __shfl_xor_sync(0xffffffffu, mn0, 1));
        mn0 = fmaxf(mn0, __shfl_xor_sync(0xffffffffu, mn0, 2));
        mn1 = fmaxf(mn1, __shfl_xor_sync(0xffffffffu, mn1, 1));
        mn1 = fmaxf(mn1, __shfl_xor_sync(0xffffffffu, mn1, 2));
        float ts0 = 0.f, ts1 = 0.f;
#pragma unroll
        for (int nt = 0; nt < 8; nt++) {
            ts0 += __expf(acc[nt][0] - mn0) + __expf(acc[nt][1] - mn0);
            ts1 += __expf(acc[nt][2] - mn1) + __expf(acc[nt][3] - mn1);
        }
        ts0 += __shfl_xor_sync(0xffffffffu, ts0, 1);
        ts0 += __shfl_xor_sync(0xffffffffu, ts0, 2);
        ts1 += __shfl_xor_sync(0xffffffffu, ts1, 1);
        ts1 += __shfl_xor_sync(0xffffffffu, ts1, 2);
        lrow[0] = lrow[0] * __expf(mrow[0] - mn0) + ts0;  mrow[0] = mn0;
        lrow[1] = lrow[1] * __expf(mrow[1] - mn1) + ts1;  mrow[1] = mn1;
#pragma unroll
        for (int nt = 0; nt < 8; nt++) {
            int c = kt*KTILE + nt*8 + tig*2;
            *(float2*)&srow[(size_t)r0 * SEQ + c] = make_float2(acc[nt][0], acc[nt][1]);
            *(float2*)&srow[(size_t)r1 * SEQ + c] = make_float2(acc[nt][2], acc[nt][3]);
        }
        __syncthreads();
    }

    const float inv0 = 1.0f / lrow[0];
    const float inv1 = 1.0f / lrow[1];

    // ======================= PASS B: attn + E@V ===========================
    float co[8][4];
#pragma unroll
    for (int nt = 0; nt < 8; nt++)
#pragma unroll
        for (int q = 0; q < 4; q++) co[nt][q] = 0.f;

    stage_hl(vp + (size_t)(NKT-1)*KTILE*DK, buf1, tid, 72);  // V tile 31 -> buf1
    __syncthreads();

    for (int kt = NKT - 1; kt >= 0; kt--) {
        float* cur = (kt & 1) ? buf1 : buf0;
        if (kt > 0)
            stage_hl(vp + (size_t)(kt-1)*KTILE*DK,
                     ((kt-1) & 1) ? buf1 : buf0, tid, 72);

        const float* Vh = cur;
        const float* Vl = cur + LO_OFF;

#pragma unroll
        for (int ks = 0; ks < 8; ks++) {
            const size_t c0 = (size_t)kt*KTILE + ks*8 + tig;
            float s0 = srow[(size_t)r0 * SEQ + c0];
            float s1 = srow[(size_t)r1 * SEQ + c0];
            float s2 = srow[(size_t)r0 * SEQ + c0 + 4];
            float s3 = srow[(size_t)r1 * SEQ + c0 + 4];
            float e0 = __expf(s0 - mrow[0]) * inv0;
            float e1 = __expf(s1 - mrow[1]) * inv1;
            float e2 = __expf(s2 - mrow[0]) * inv0;
            float e3 = __expf(s3 - mrow[1]) * inv1;
            arow[(size_t)r0 * SEQ + c0]     = e0;
            arow[(size_t)r1 * SEQ + c0]     = e1;
            arow[(size_t)r0 * SEQ + c0 + 4] = e2;
            arow[(size_t)r1 * SEQ + c0 + 4] = e3;
            uint32_t aeh[4], ael[4];
            aeh[0] = cvt_tf32(e0); ael[0] = cvt_tf32(e0 - __uint_as_float(aeh[0]));
            aeh[1] = cvt_tf32(e1); ael[1] = cvt_tf32(e1 - __uint_as_float(aeh[1]));
            aeh[2] = cvt_tf32(e2); ael[2] = cvt_tf32(e2 - __uint_as_float(aeh[2]));
            aeh[3] = cvt_tf32(e3); ael[3] = cvt_tf32(e3 - __uint_as_float(aeh[3]));
#pragma unroll
            for (int nt = 0; nt < 8; nt++) {
                uint32_t bhv[2], blv[2];
                bhv[0] = __float_as_uint(Vh[(ks*8 + tig)*72 + nt*8 + g]);
                bhv[1] = __float_as_uint(Vh[(ks*8 + tig + 4)*72 + nt*8 + g]);
                blv[0] = __float_as_uint(Vl[(ks*8 + tig)*72 + nt*8 + g]);
                blv[1] = __float_as_uint(Vl[(ks*8 + tig + 4)*72 + nt*8 + g]);
                mma8(co[nt], aeh, bhv);
                mma8(co[nt], aeh, blv);
                mma8(co[nt], ael, bhv);
            }
        }
        __syncthreads();
    }

    // write ctx [B,S,D]
#pragma unroll
    for (int nt = 0; nt < 8; nt++) {
        int d = nt*8 + tig*2;
        *(float2*)&g_ctx[((size_t)(b*SEQ) + qr0 + r0) * DMODEL + h*DK + d] =
            make_float2(co[nt][0], co[nt][1]);
        *(float2*)&g_ctx[((size_t)(b*SEQ) + qr0 + r1) * DMODEL + h*DK + d] =
            make_float2(co[nt][2], co[nt][3]);
    }
}

// ============================================================================
extern "C" void kernel_launch(void* const* d_in, const int* in_sizes, int n_in,
                              void* d_out, int out_size)
{
    const float* Q  = (const float*)d_in[0];
    const float* K  = (const float*)d_in[1];
    const float* V  = (const float*)d_in[2];
    const unsigned char* mask = (const unsigned char*)d_in[3];
    const float* Wq = (const float*)d_in[4];  const float* bq = (const float*)d_in[5];
    const float* Wk = (const float*)d_in[6];  const float* bk = (const float*)d_in[7];
    const float* Wv = (const float*)d_in[8];  const float* bv = (const float*)d_in[9];
    const float* Wo = (const float*)d_in[10]; const float* bo = (const float*)d_in[11];

    float* out    = (float*)d_out;
    float* attn   = out + (size_t)NTOK * DMODEL;
    float* scores = attn + (size_t)BATCH * NHEADS * SEQ * SEQ;

    cudaFuncSetAttribute(k_attn_mma, cudaFuncAttributeMaxDynamicSharedMemorySize,
                         ATTN_SMEM);

    dim3 gp(NTOK / 128, DMODEL / 128, 3);       // 32 x 8 x 3
    k_projmma<<<gp, 256>>>(Q, K, V, Wq, Wk, Wv, bq, bk, bv);

    dim3 gf(SEQ / 128, BATCH * NHEADS);         // 16 x 32
    k_attn_mma<<<gf, 256, ATTN_SMEM>>>(mask, scores, attn);

    dim3 go(NTOK / 128, DMODEL / 128);          // 32 x 8
    k_outmma<<<go, 256>>>(Wo, bo, Q, out);
}